// round 7
// baseline (speedup 1.0000x reference)
#include <cuda_runtime.h>
#include <cuda_fp16.h>
#include <cstdint>

// ---------------------------------------------------------------------------
// Ragged batched QK^T (static): B=32, H=16, E=64, SEQLEN[i]=256+(37i)%257,
// out = concat_b [H, L_b, L_b], scale = 0.125.
// fp16 m16n8k16 mma.sync; 128x128 tile per CTA; per-warp 32x64 output
// processed in two 32x32 halves (32-reg accumulator) -> 3 CTAs/SM.
// ---------------------------------------------------------------------------
#define NB 32
#define NH 16
#define NE 64
#define BM 128
#define BN 128
#define TPAD 144                    // bytes per fp16 smem tile row (128+16 pad)
#define TILEB (BM * TPAD)           // 18432 B
#define SSTR 34                     // staging stride (floats) — MUST be even
#define SWARP (32 * SSTR)           // staging floats per warp (1088)

struct Tables {
    int seqlen[NB];
    int tok_base[NB];
    long long out_base[NB];
    int blk_base[NB + 1];
};

constexpr Tables make_tables() {
    Tables t{};
    int tb = 0; long long ob = 0; int bb = 0;
    for (int i = 0; i < NB; i++) {
        int L = 256 + (i * 37) % 257;
        t.seqlen[i] = L; t.tok_base[i] = tb; t.out_base[i] = ob; t.blk_base[i] = bb;
        int nt = (L + BM - 1) / BM;
        tb += L; ob += (long long)NH * L * L; bb += NH * nt * nt;
    }
    t.blk_base[NB] = bb;
    return t;
}

__constant__ Tables dtab = make_tables();

__device__ __forceinline__ uint32_t cvta_sm(const void* p) {
    uint32_t a;
    asm("{ .reg .u64 t; cvta.to.shared.u64 t, %1; cvt.u32.u64 %0, t; }"
        : "=r"(a) : "l"(p));
    return a;
}

__device__ __forceinline__ void ldm4(uint32_t* r, uint32_t addr) {
    asm volatile(
        "ldmatrix.sync.aligned.m8n8.x4.shared.b16 {%0,%1,%2,%3}, [%4];"
        : "=r"(r[0]), "=r"(r[1]), "=r"(r[2]), "=r"(r[3]) : "r"(addr));
}

__device__ __forceinline__ void mma_f16(float* d, const uint32_t* a,
                                        uint32_t b0, uint32_t b1) {
    asm volatile(
        "mma.sync.aligned.m16n8k16.row.col.f32.f16.f16.f32 "
        "{%0,%1,%2,%3}, {%4,%5,%6,%7}, {%8,%9}, {%0,%1,%2,%3};"
        : "+f"(d[0]), "+f"(d[1]), "+f"(d[2]), "+f"(d[3])
        : "r"(a[0]), "r"(a[1]), "r"(a[2]), "r"(a[3]), "r"(b0), "r"(b1));
}

__global__ __launch_bounds__(256, 3) void bmm1_fp16(
    const float* __restrict__ Q,
    const float* __restrict__ K,
    float* __restrict__ out)
{
    extern __shared__ __align__(16) char sm[];
    char* smQ = sm;                           // fp16 [128][TPAD]
    char* smK = sm + TILEB;
    float* stage = (float*)(sm + 2 * TILEB);  // 8 warps x SWARP floats

    const int bid = blockIdx.x;

    // ---- locate (batch, head, qtile, ktile) ----
    int b = 0;
#pragma unroll
    for (int i = 1; i < NB; i++) b += (bid >= dtab.blk_base[i]);
    const int L  = dtab.seqlen[b];
    const int nt = (L + 127) >> 7;
    int rem = bid - dtab.blk_base[b];
    const int h  = rem / (nt * nt);
    rem -= h * (nt * nt);
    const int qt = rem / nt;
    const int kt = rem - qt * nt;

    const int tid = threadIdx.x;
    const long long rowstride = (long long)NH * NE;   // 1024 floats/token
    const float* qbase = Q + (long long)dtab.tok_base[b] * rowstride + h * NE;
    const float* kbase = K + (long long)dtab.tok_base[b] * rowstride + h * NE;

    // ---- global f32 -> smem fp16 tiles (inline rn convert, zero-fill) ----
    {
        const int c4 = tid & 15;
        const int rl = tid >> 4;
#pragma unroll
        for (int g = 0; g < 8; g++) {
            const int m = rl + g * 16;

            const int qrow = qt * BM + m;
            float4 v = (qrow < L)
                ? *(const float4*)(qbase + (long long)qrow * rowstride + c4 * 4)
                : make_float4(0.f, 0.f, 0.f, 0.f);
            __half2 h0 = __floats2half2_rn(v.x, v.y);
            __half2 h1 = __floats2half2_rn(v.z, v.w);
            *(uint2*)(smQ + m * TPAD + c4 * 8) =
                make_uint2(*(uint32_t*)&h0, *(uint32_t*)&h1);

            const int krow = kt * BN + m;
            float4 u = (krow < L)
                ? *(const float4*)(kbase + (long long)krow * rowstride + c4 * 4)
                : make_float4(0.f, 0.f, 0.f, 0.f);
            h0 = __floats2half2_rn(u.x, u.y);
            h1 = __floats2half2_rn(u.z, u.w);
            *(uint2*)(smK + m * TPAD + c4 * 8) =
                make_uint2(*(uint32_t*)&h0, *(uint32_t*)&h1);
        }
    }
    __syncthreads();

    // ---- warp layout: 8 warps = 4(m) x 2(n); warp tile 32m x 64n,
    //      processed as two 32m x 32n halves ----
    const int wid = tid >> 5, l = tid & 31;
    const int wm = wid & 3, wn = wid >> 2;

    const uint32_t smbase = cvta_sm(sm);
    const uint32_t a_off = smbase
        + (wm * 32 + (l & 7) + ((l >> 3) & 1) * 8) * TPAD
        + ((l >> 4) & 1) * 16;
    uint32_t b_off[4];
#pragma unroll
    for (int j = 0; j < 4; j++)
        b_off[j] = smbase + TILEB
            + (wn * 64 + j * 16 + (l & 7) + ((l >> 4) & 1) * 8) * TPAD
            + ((l >> 3) & 1) * 16;

    const float sc = 0.125f;
    float* wst = stage + wid * SWARP;
    const int q0w = qt * BM + wm * 32;
    const int n0w = kt * BN + wn * 64;
    const long long obase = dtab.out_base[b] + (long long)h * L * L;
    const int rmax = min(32, L - q0w);

#pragma unroll 1
    for (int hf = 0; hf < 2; hf++) {
        float acc[2][4][4];
#pragma unroll
        for (int mi = 0; mi < 2; mi++)
#pragma unroll
            for (int ni = 0; ni < 4; ni++)
#pragma unroll
                for (int r = 0; r < 4; r++) acc[mi][ni][r] = 0.f;

#pragma unroll
        for (int ks = 0; ks < 4; ks++) {          // 4 k-steps of 16
            const uint32_t koff = ks * 32;        // 16 halves = 32B
            uint32_t A0[4], A1[4], B0[4], B1[4];
            ldm4(A0, a_off + koff);
            ldm4(A1, a_off + 16 * TPAD + koff);
            ldm4(B0, b_off[hf * 2 + 0] + koff);
            ldm4(B1, b_off[hf * 2 + 1] + koff);
#pragma unroll
            for (int ni = 0; ni < 4; ni++) {
                const uint32_t* Bf = (ni < 2) ? B0 : B1;
                const uint32_t b0 = Bf[(ni & 1) * 2];
                const uint32_t b1 = Bf[(ni & 1) * 2 + 1];
                mma_f16(acc[0][ni], A0, b0, b1);
                mma_f16(acc[1][ni], A1, b0, b1);
            }
        }

        // ---- staged coalesced epilogue for this 32x32 half ----
        __syncwarp();
#pragma unroll
        for (int mi = 0; mi < 2; mi++)
#pragma unroll
            for (int h2 = 0; h2 < 2; h2++)
#pragma unroll
                for (int ni = 0; ni < 4; ni++) {
                    const int r = mi * 16 + h2 * 8 + (l >> 2);
                    const int c = ni * 8 + 2 * (l & 3);
                    *(float2*)&wst[r * SSTR + c] =
                        make_float2(acc[mi][ni][h2 * 2 + 0] * sc,
                                    acc[mi][ni][h2 * 2 + 1] * sc);
                }
        __syncwarp();

        const int n = n0w + hf * 32 + l;
        const bool nv = n < L;
        const float* src = wst + l;
        float* dst = out + obase + (long long)q0w * L + n;
#pragma unroll 8
        for (int r = 0; r < rmax; r++) {
            const float v = src[r * SSTR];
            if (nv) dst[(long long)r * L] = v;
        }
    }
}

extern "C" void kernel_launch(void* const* d_in, const int* in_sizes, int n_in,
                              void* d_out, int out_size)
{
    const float* q = (const float*)d_in[0];
    const float* k = (const float*)d_in[1];
    float* o = (float*)d_out;

    constexpr Tables ht = make_tables();
    const int nblocks = ht.blk_base[NB];     // 5872

    constexpr int smem = 2 * TILEB + 8 * SWARP * (int)sizeof(float); // 71680
    cudaFuncSetAttribute(bmm1_fp16,
                         cudaFuncAttributeMaxDynamicSharedMemorySize, smem);
    bmm1_fp16<<<nblocks, 256, smem>>>(q, k, o);
}

// round 8
// speedup vs baseline: 1.0925x; 1.0925x over previous
#include <cuda_runtime.h>
#include <cuda_fp16.h>
#include <cstdint>

// ---------------------------------------------------------------------------
// Ragged batched QK^T (static): B=32, H=16, E=64, SEQLEN[i]=256+(37i)%257,
// out = concat_b [H, L_b, L_b], scale = 0.125.
// fp16 m16n8k16 mma.sync. One CTA per (b,h,qt) 128-row output stripe,
// looping kt with double-buffered K smem (K load hidden behind MMA).
// Full 64-reg accumulator (round-4 proven), staged coalesced epilogue.
// ---------------------------------------------------------------------------
#define NB 32
#define NH 16
#define NE 64
#define BM 128
#define BN 128
#define TPAD 144                    // bytes per fp16 smem tile row (128+16 pad)
#define TILEB (BM * TPAD)           // 18432 B
#define SSTR 34                     // staging stride (floats) — even
#define SWARP (32 * SSTR)           // staging floats per warp

struct Tables {
    int seqlen[NB];
    int tok_base[NB];
    long long out_base[NB];
    int blk_base[NB + 1];           // prefix of H * nt  (stripe count)
};

constexpr Tables make_tables() {
    Tables t{};
    int tb = 0; long long ob = 0; int bb = 0;
    for (int i = 0; i < NB; i++) {
        int L = 256 + (i * 37) % 257;
        t.seqlen[i] = L; t.tok_base[i] = tb; t.out_base[i] = ob; t.blk_base[i] = bb;
        int nt = (L + BM - 1) / BM;
        tb += L; ob += (long long)NH * L * L; bb += NH * nt;
    }
    t.blk_base[NB] = bb;
    return t;
}

__constant__ Tables dtab = make_tables();

__device__ __forceinline__ uint32_t cvta_sm(const void* p) {
    uint32_t a;
    asm("{ .reg .u64 t; cvta.to.shared.u64 t, %1; cvt.u32.u64 %0, t; }"
        : "=r"(a) : "l"(p));
    return a;
}

__device__ __forceinline__ void ldm4(uint32_t* r, uint32_t addr) {
    asm volatile(
        "ldmatrix.sync.aligned.m8n8.x4.shared.b16 {%0,%1,%2,%3}, [%4];"
        : "=r"(r[0]), "=r"(r[1]), "=r"(r[2]), "=r"(r[3]) : "r"(addr));
}

__device__ __forceinline__ void mma_f16(float* d, const uint32_t* a,
                                        uint32_t b0, uint32_t b1) {
    asm volatile(
        "mma.sync.aligned.m16n8k16.row.col.f32.f16.f16.f32 "
        "{%0,%1,%2,%3}, {%4,%5,%6,%7}, {%8,%9}, {%0,%1,%2,%3};"
        : "+f"(d[0]), "+f"(d[1]), "+f"(d[2]), "+f"(d[3])
        : "r"(a[0]), "r"(a[1]), "r"(a[2]), "r"(a[3]), "r"(b0), "r"(b1));
}

// load one 128-row tile (f32 gmem -> fp16 smem, zero-fill past L)
__device__ __forceinline__ void load_tile(const float* __restrict__ base,
                                          int row0, int L, char* dst, int tid)
{
    const long long rowstride = (long long)NH * NE;
    const int c4 = tid & 15;
    const int rl = tid >> 4;
#pragma unroll
    for (int g = 0; g < 8; g++) {
        const int m = rl + g * 16;
        const int grow = row0 + m;
        float4 v = (grow < L)
            ? *(const float4*)(base + (long long)grow * rowstride + c4 * 4)
            : make_float4(0.f, 0.f, 0.f, 0.f);
        __half2 h0 = __floats2half2_rn(v.x, v.y);
        __half2 h1 = __floats2half2_rn(v.z, v.w);
        *(uint2*)(dst + m * TPAD + c4 * 8) =
            make_uint2(*(uint32_t*)&h0, *(uint32_t*)&h1);
    }
}

__global__ __launch_bounds__(256, 2) void bmm1_fp16(
    const float* __restrict__ Q,
    const float* __restrict__ K,
    float* __restrict__ out)
{
    extern __shared__ __align__(16) char sm[];
    char* smQ = sm;                             // fp16 [128][TPAD]
    char* smK[2] = { sm + TILEB, sm + 2 * TILEB };
    float* stage = (float*)(sm + 3 * TILEB);    // 8 warps x SWARP floats

    const int bid = blockIdx.x;

    // ---- locate (batch, head, qtile) ----
    int b = 0;
#pragma unroll
    for (int i = 1; i < NB; i++) b += (bid >= dtab.blk_base[i]);
    const int L  = dtab.seqlen[b];
    const int nt = (L + 127) >> 7;
    int rem = bid - dtab.blk_base[b];
    const int h  = rem / nt;
    const int qt = rem - h * nt;

    const int tid = threadIdx.x;
    const float* qbase = Q + (long long)dtab.tok_base[b] * NH * NE + h * NE;
    const float* kbase = K + (long long)dtab.tok_base[b] * NH * NE + h * NE;

    // ---- load Q stripe tile once + preload K tile 0 ----
    load_tile(qbase, qt * BM, L, smQ, tid);
    load_tile(kbase, 0, L, smK[0], tid);
    __syncthreads();

    // ---- warp layout: 8 warps = 4(m) x 2(n); warp tile 32m x 64n ----
    const int wid = tid >> 5, l = tid & 31;
    const int wm = wid & 3, wn = wid >> 2;

    const uint32_t smbase = cvta_sm(sm);
    const uint32_t a_off = smbase
        + (wm * 32 + (l & 7) + ((l >> 3) & 1) * 8) * TPAD
        + ((l >> 4) & 1) * 16;
    // B fragment offsets relative to a K-buffer base
    uint32_t b_rel[4];
#pragma unroll
    for (int j = 0; j < 4; j++)
        b_rel[j] = (wn * 64 + j * 16 + (l & 7) + ((l >> 4) & 1) * 8) * TPAD
                 + ((l >> 3) & 1) * 16;

    const float sc = 0.125f;
    float* wst = stage + wid * SWARP;
    const int q0w = qt * BM + wm * 32;
    const long long obase = dtab.out_base[b] + (long long)h * L * L;
    const int rmax = min(32, L - q0w);
    const bool active = rmax > 0;

    for (int kt = 0, buf = 0; kt < nt; kt++, buf ^= 1) {
        // prefetch K tile kt+1 into the other buffer (overlaps with MMA)
        if (kt + 1 < nt)
            load_tile(kbase, (kt + 1) * BM, L, smK[buf ^ 1], tid);

        if (active) {
            const uint32_t kb = smbase + (uint32_t)(TILEB + buf * TILEB);

            float acc[2][8][4];
#pragma unroll
            for (int mi = 0; mi < 2; mi++)
#pragma unroll
                for (int ni = 0; ni < 8; ni++)
#pragma unroll
                    for (int r = 0; r < 4; r++) acc[mi][ni][r] = 0.f;

#pragma unroll
            for (int ks = 0; ks < 4; ks++) {          // 4 k-steps of 16
                const uint32_t koff = ks * 32;
                uint32_t A0[4], A1[4], Bf[4][4];
                ldm4(A0, a_off + koff);
                ldm4(A1, a_off + 16 * TPAD + koff);
#pragma unroll
                for (int j = 0; j < 4; j++) ldm4(Bf[j], kb + b_rel[j] + koff);
#pragma unroll
                for (int ni = 0; ni < 8; ni++) {
                    const uint32_t b0 = Bf[ni >> 1][(ni & 1) * 2];
                    const uint32_t b1 = Bf[ni >> 1][(ni & 1) * 2 + 1];
                    mma_f16(acc[0][ni], A0, b0, b1);
                    mma_f16(acc[1][ni], A1, b0, b1);
                }
            }

            // ---- staged coalesced epilogue (two 32-col halves) ----
            const int n0w = kt * BN + wn * 64;
#pragma unroll
            for (int hf = 0; hf < 2; hf++) {
                __syncwarp();
#pragma unroll
                for (int mi = 0; mi < 2; mi++)
#pragma unroll
                    for (int h2 = 0; h2 < 2; h2++)
#pragma unroll
                        for (int ni4 = 0; ni4 < 4; ni4++) {
                            const int ni = hf * 4 + ni4;
                            const int r = mi * 16 + h2 * 8 + (l >> 2);
                            const int c = ni4 * 8 + 2 * (l & 3);
                            *(float2*)&wst[r * SSTR + c] =
                                make_float2(acc[mi][ni][h2 * 2 + 0] * sc,
                                            acc[mi][ni][h2 * 2 + 1] * sc);
                        }
                __syncwarp();

                const int n = n0w + hf * 32 + l;
                const bool nv = n < L;
                const float* src = wst + l;
                float* dst = out + obase + (long long)q0w * L + n;
#pragma unroll 8
                for (int r = 0; r < rmax; r++) {
                    const float v = src[r * SSTR];
                    if (nv) dst[(long long)r * L] = v;
                }
            }
        }

        __syncthreads();   // next buffer complete; current buffer reads done
    }
}

extern "C" void kernel_launch(void* const* d_in, const int* in_sizes, int n_in,
                              void* d_out, int out_size)
{
    const float* q = (const float*)d_in[0];
    const float* k = (const float*)d_in[1];
    float* o = (float*)d_out;

    constexpr Tables ht = make_tables();
    const int nblocks = ht.blk_base[NB];     // 16 * sum(nt)

    constexpr int smem = 3 * TILEB + 8 * SWARP * (int)sizeof(float); // 90112
    cudaFuncSetAttribute(bmm1_fp16,
                         cudaFuncAttributeMaxDynamicSharedMemorySize, smem);
    bmm1_fp16<<<nblocks, 256, smem>>>(q, k, o);
}

// round 9
// speedup vs baseline: 1.1927x; 1.0917x over previous
#include <cuda_runtime.h>
#include <cuda_fp16.h>
#include <cstdint>

// ---------------------------------------------------------------------------
// Ragged batched QK^T (static): B=32, H=16, E=64, SEQLEN[i]=256+(37i)%257,
// out = concat_b [H, L_b, L_b], scale = 0.125.
// fp16 m16n8k16 mma.sync; one 128x128 tile per CTA (round-4 core);
// epilogue stores fragments DIRECTLY to gmem (no smem staging round-trip):
//   even L -> proven 8B-aligned float2 stores; odd L -> paired STG.32.
// ---------------------------------------------------------------------------
#define NB 32
#define NH 16
#define NE 64
#define BM 128
#define BN 128
#define TPAD 144                    // bytes per fp16 smem tile row (128+16 pad)
#define TILEB (BM * TPAD)           // 18432 B

struct Tables {
    int seqlen[NB];
    int tok_base[NB];
    long long out_base[NB];
    int blk_base[NB + 1];
};

constexpr Tables make_tables() {
    Tables t{};
    int tb = 0; long long ob = 0; int bb = 0;
    for (int i = 0; i < NB; i++) {
        int L = 256 + (i * 37) % 257;
        t.seqlen[i] = L; t.tok_base[i] = tb; t.out_base[i] = ob; t.blk_base[i] = bb;
        int nt = (L + BM - 1) / BM;
        tb += L; ob += (long long)NH * L * L; bb += NH * nt * nt;
    }
    t.blk_base[NB] = bb;
    return t;
}

__constant__ Tables dtab = make_tables();

__device__ __forceinline__ uint32_t cvta_sm(const void* p) {
    uint32_t a;
    asm("{ .reg .u64 t; cvta.to.shared.u64 t, %1; cvt.u32.u64 %0, t; }"
        : "=r"(a) : "l"(p));
    return a;
}

__device__ __forceinline__ void ldm4(uint32_t* r, uint32_t addr) {
    asm volatile(
        "ldmatrix.sync.aligned.m8n8.x4.shared.b16 {%0,%1,%2,%3}, [%4];"
        : "=r"(r[0]), "=r"(r[1]), "=r"(r[2]), "=r"(r[3]) : "r"(addr));
}

__device__ __forceinline__ void mma_f16(float* d, const uint32_t* a,
                                        uint32_t b0, uint32_t b1) {
    asm volatile(
        "mma.sync.aligned.m16n8k16.row.col.f32.f16.f16.f32 "
        "{%0,%1,%2,%3}, {%4,%5,%6,%7}, {%8,%9}, {%0,%1,%2,%3};"
        : "+f"(d[0]), "+f"(d[1]), "+f"(d[2]), "+f"(d[3])
        : "r"(a[0]), "r"(a[1]), "r"(a[2]), "r"(a[3]), "r"(b0), "r"(b1));
}

__global__ __launch_bounds__(256, 2) void bmm1_fp16(
    const float* __restrict__ Q,
    const float* __restrict__ K,
    float* __restrict__ out)
{
    extern __shared__ __align__(16) char sm[];
    char* smQ = sm;                           // fp16 [128][TPAD]
    char* smK = sm + TILEB;

    const int bid = blockIdx.x;

    // ---- locate (batch, head, qtile, ktile) ----
    int b = 0;
#pragma unroll
    for (int i = 1; i < NB; i++) b += (bid >= dtab.blk_base[i]);
    const int L  = dtab.seqlen[b];
    const int nt = (L + 127) >> 7;
    int rem = bid - dtab.blk_base[b];
    const int h  = rem / (nt * nt);
    rem -= h * (nt * nt);
    const int qt = rem / nt;
    const int kt = rem - qt * nt;

    const int tid = threadIdx.x;
    const long long rowstride = (long long)NH * NE;   // 1024 floats/token
    const float* qbase = Q + (long long)dtab.tok_base[b] * rowstride + h * NE;
    const float* kbase = K + (long long)dtab.tok_base[b] * rowstride + h * NE;

    // ---- global f32 -> smem fp16 tiles (inline rn convert, zero-fill) ----
    {
        const int c4 = tid & 15;
        const int rl = tid >> 4;
#pragma unroll
        for (int g = 0; g < 8; g++) {
            const int m = rl + g * 16;

            const int qrow = qt * BM + m;
            float4 v = (qrow < L)
                ? *(const float4*)(qbase + (long long)qrow * rowstride + c4 * 4)
                : make_float4(0.f, 0.f, 0.f, 0.f);
            __half2 h0 = __floats2half2_rn(v.x, v.y);
            __half2 h1 = __floats2half2_rn(v.z, v.w);
            *(uint2*)(smQ + m * TPAD + c4 * 8) =
                make_uint2(*(uint32_t*)&h0, *(uint32_t*)&h1);

            const int krow = kt * BN + m;
            float4 u = (krow < L)
                ? *(const float4*)(kbase + (long long)krow * rowstride + c4 * 4)
                : make_float4(0.f, 0.f, 0.f, 0.f);
            h0 = __floats2half2_rn(u.x, u.y);
            h1 = __floats2half2_rn(u.z, u.w);
            *(uint2*)(smK + m * TPAD + c4 * 8) =
                make_uint2(*(uint32_t*)&h0, *(uint32_t*)&h1);
        }
    }
    __syncthreads();

    // ---- warp layout: 8 warps = 4(m) x 2(n); warp tile 32m x 64n ----
    const int wid = tid >> 5, l = tid & 31;
    const int wm = wid & 3, wn = wid >> 2;

    const uint32_t smbase = cvta_sm(sm);
    const uint32_t a_off = smbase
        + (wm * 32 + (l & 7) + ((l >> 3) & 1) * 8) * TPAD
        + ((l >> 4) & 1) * 16;
    uint32_t b_off[4];
#pragma unroll
    for (int j = 0; j < 4; j++)
        b_off[j] = smbase + TILEB
            + (wn * 64 + j * 16 + (l & 7) + ((l >> 4) & 1) * 8) * TPAD
            + ((l >> 3) & 1) * 16;

    float acc[2][8][4];
#pragma unroll
    for (int mi = 0; mi < 2; mi++)
#pragma unroll
        for (int ni = 0; ni < 8; ni++)
#pragma unroll
            for (int r = 0; r < 4; r++) acc[mi][ni][r] = 0.f;

#pragma unroll
    for (int ks = 0; ks < 4; ks++) {          // 4 k-steps of 16
        const uint32_t koff = ks * 32;        // 16 halves = 32B
        uint32_t A0[4], A1[4], Bf[4][4];
        ldm4(A0, a_off + koff);
        ldm4(A1, a_off + 16 * TPAD + koff);
#pragma unroll
        for (int j = 0; j < 4; j++) ldm4(Bf[j], b_off[j] + koff);
#pragma unroll
        for (int ni = 0; ni < 8; ni++) {
            const uint32_t b0 = Bf[ni >> 1][(ni & 1) * 2];
            const uint32_t b1 = Bf[ni >> 1][(ni & 1) * 2 + 1];
            mma_f16(acc[0][ni], A0, b0, b1);
            mma_f16(acc[1][ni], A1, b0, b1);
        }
    }

    // ---- epilogue: direct fragment stores, no smem staging ----
    // lane l covers rows q0+{0,8,16,24}, cols n0 + 8*ni, n0 = 2*(l&3).
    // Per warp-instruction: 8 rows x 32B contiguous = 8 full sectors.
    const float sc = 0.125f;
    const long long obase = dtab.out_base[b] + (long long)h * L * L;
    const int q0 = qt * BM + wm * 32 + (l >> 2);
    const int n0 = kt * BN + wn * 64 + 2 * (l & 3);

    if (L & 1) {
        // odd L: row parity alternates; paired scalar stores (same wavefronts)
#pragma unroll
        for (int mi = 0; mi < 2; mi++)
#pragma unroll
            for (int h2 = 0; h2 < 2; h2++) {
                const int q = q0 + mi * 16 + h2 * 8;
                if (q >= L) continue;
                float* row = out + obase + (long long)q * L;
#pragma unroll
                for (int ni = 0; ni < 8; ni++) {
                    const int n = n0 + ni * 8;
                    const float v0 = acc[mi][ni][h2 * 2 + 0] * sc;
                    const float v1 = acc[mi][ni][h2 * 2 + 1] * sc;
                    if (n < L)     row[n]     = v0;
                    if (n + 1 < L) row[n + 1] = v1;
                }
            }
    } else {
        // even L: obase, q*L, n all even -> 8B-aligned float2 stores.
        // n+1 < L is implied by n < L (both even).
#pragma unroll
        for (int mi = 0; mi < 2; mi++)
#pragma unroll
            for (int h2 = 0; h2 < 2; h2++) {
                const int q = q0 + mi * 16 + h2 * 8;
                if (q >= L) continue;
                float* row = out + obase + (long long)q * L;
#pragma unroll
                for (int ni = 0; ni < 8; ni++) {
                    const int n = n0 + ni * 8;
                    if (n < L)
                        *(float2*)&row[n] =
                            make_float2(acc[mi][ni][h2 * 2 + 0] * sc,
                                        acc[mi][ni][h2 * 2 + 1] * sc);
                }
            }
    }
}

extern "C" void kernel_launch(void* const* d_in, const int* in_sizes, int n_in,
                              void* d_out, int out_size)
{
    const float* q = (const float*)d_in[0];
    const float* k = (const float*)d_in[1];
    float* o = (float*)d_out;

    constexpr Tables ht = make_tables();
    const int nblocks = ht.blk_base[NB];     // 5872

    constexpr int smem = 2 * TILEB;          // 36864 B
    cudaFuncSetAttribute(bmm1_fp16,
                         cudaFuncAttributeMaxDynamicSharedMemorySize, smem);
    bmm1_fp16<<<nblocks, 256, smem>>>(q, k, o);
}

// round 11
// speedup vs baseline: 1.4477x; 1.2138x over previous
#include <cuda_runtime.h>
#include <cuda_fp16.h>
#include <cstdint>

// ---------------------------------------------------------------------------
// Ragged batched QK^T (static): B=32, H=16, E=64, SEQLEN[i]=256+(37i)%257,
// out = concat_b [H, L_b, L_b], scale = 0.125.
// fp16 inputs (rn) + f32 accumulators, m16n8k16 mma.sync, one 128x128 tile
// per CTA. Single-pass width-2 staged epilogue (stride-72 staging,
// conflict-free), streaming stores. Staging overlays tile smem.
// ---------------------------------------------------------------------------
#define NB 32
#define NH 16
#define NE 64
#define BM 128
#define BN 128
#define TPAD 144                    // bytes per fp16 smem tile row (128+16 pad)
#define TILEB (BM * TPAD)           // 18432 B
#define SSTR 72                     // staging stride (floats): addr8B = 36r+c
#define SWARP (32 * SSTR)           // staging floats per warp (2304)

struct Tables {
    int seqlen[NB];
    int tok_base[NB];
    long long out_base[NB];
    int blk_base[NB + 1];
};

constexpr Tables make_tables() {
    Tables t{};
    int tb = 0; long long ob = 0; int bb = 0;
    for (int i = 0; i < NB; i++) {
        int L = 256 + (i * 37) % 257;
        t.seqlen[i] = L; t.tok_base[i] = tb; t.out_base[i] = ob; t.blk_base[i] = bb;
        int nt = (L + BM - 1) / BM;
        tb += L; ob += (long long)NH * L * L; bb += NH * nt * nt;
    }
    t.blk_base[NB] = bb;
    return t;
}

__constant__ Tables dtab = make_tables();

__device__ __forceinline__ uint32_t cvta_sm(const void* p) {
    uint32_t a;
    asm("{ .reg .u64 t; cvta.to.shared.u64 t, %1; cvt.u32.u64 %0, t; }"
        : "=r"(a) : "l"(p));
    return a;
}

__device__ __forceinline__ void ldm4(uint32_t* r, uint32_t addr) {
    asm volatile(
        "ldmatrix.sync.aligned.m8n8.x4.shared.b16 {%0,%1,%2,%3}, [%4];"
        : "=r"(r[0]), "=r"(r[1]), "=r"(r[2]), "=r"(r[3]) : "r"(addr));
}

__device__ __forceinline__ void mma_f16(float* d, const uint32_t* a,
                                        uint32_t b0, uint32_t b1) {
    asm volatile(
        "mma.sync.aligned.m16n8k16.row.col.f32.f16.f16.f32 "
        "{%0,%1,%2,%3}, {%4,%5,%6,%7}, {%8,%9}, {%0,%1,%2,%3};"
        : "+f"(d[0]), "+f"(d[1]), "+f"(d[2]), "+f"(d[3])
        : "r"(a[0]), "r"(a[1]), "r"(a[2]), "r"(a[3]), "r"(b0), "r"(b1));
}

__global__ __launch_bounds__(256, 2) void bmm1_fp16(
    const float* __restrict__ Q,
    const float* __restrict__ K,
    float* __restrict__ out)
{
    extern __shared__ __align__(16) char sm[];
    char* smQ = sm;                           // fp16 [128][TPAD]
    char* smK = sm + TILEB;

    const int bid = blockIdx.x;

    // ---- locate (batch, head, qtile, ktile) ----
    int b = 0;
#pragma unroll
    for (int i = 1; i < NB; i++) b += (bid >= dtab.blk_base[i]);
    const int L  = dtab.seqlen[b];
    const int nt = (L + 127) >> 7;
    int rem = bid - dtab.blk_base[b];
    const int h  = rem / (nt * nt);
    rem -= h * (nt * nt);
    const int qt = rem / nt;
    const int kt = rem - qt * nt;

    const int tid = threadIdx.x;
    const long long rowstride = (long long)NH * NE;   // 1024 floats/token
    const float* qbase = Q + (long long)dtab.tok_base[b] * rowstride + h * NE;
    const float* kbase = K + (long long)dtab.tok_base[b] * rowstride + h * NE;

    // ---- global f32 -> smem fp16 tiles (inline rn convert, zero-fill) ----
    {
        const int c4 = tid & 15;
        const int rl = tid >> 4;
#pragma unroll
        for (int g = 0; g < 8; g++) {
            const int m = rl + g * 16;

            const int qrow = qt * BM + m;
            float4 v = (qrow < L)
                ? *(const float4*)(qbase + (long long)qrow * rowstride + c4 * 4)
                : make_float4(0.f, 0.f, 0.f, 0.f);
            __half2 h0 = __floats2half2_rn(v.x, v.y);
            __half2 h1 = __floats2half2_rn(v.z, v.w);
            *(uint2*)(smQ + m * TPAD + c4 * 8) =
                make_uint2(*(uint32_t*)&h0, *(uint32_t*)&h1);

            const int krow = kt * BN + m;
            float4 u = (krow < L)
                ? *(const float4*)(kbase + (long long)krow * rowstride + c4 * 4)
                : make_float4(0.f, 0.f, 0.f, 0.f);
            h0 = __floats2half2_rn(u.x, u.y);
            h1 = __floats2half2_rn(u.z, u.w);
            *(uint2*)(smK + m * TPAD + c4 * 8) =
                make_uint2(*(uint32_t*)&h0, *(uint32_t*)&h1);
        }
    }
    __syncthreads();

    // ---- warp layout: 8 warps = 4(m) x 2(n); warp tile 32m x 64n ----
    const int wid = tid >> 5, l = tid & 31;
    const int wm = wid & 3, wn = wid >> 2;

    const uint32_t smbase = cvta_sm(sm);
    const uint32_t a_off = smbase
        + (wm * 32 + (l & 7) + ((l >> 3) & 1) * 8) * TPAD
        + ((l >> 4) & 1) * 16;
    uint32_t b_off[4];
#pragma unroll
    for (int j = 0; j < 4; j++)
        b_off[j] = smbase + TILEB
            + (wn * 64 + j * 16 + (l & 7) + ((l >> 4) & 1) * 8) * TPAD
            + ((l >> 3) & 1) * 16;

    float acc[2][8][4];
#pragma unroll
    for (int mi = 0; mi < 2; mi++)
#pragma unroll
        for (int ni = 0; ni < 8; ni++)
#pragma unroll
            for (int r = 0; r < 4; r++) acc[mi][ni][r] = 0.f;

#pragma unroll
    for (int ks = 0; ks < 4; ks++) {          // 4 k-steps of 16
        const uint32_t koff = ks * 32;        // 16 halves = 32B
        uint32_t A0[4], A1[4], Bf[4][4];
        ldm4(A0, a_off + koff);
        ldm4(A1, a_off + 16 * TPAD + koff);
#pragma unroll
        for (int j = 0; j < 4; j++) ldm4(Bf[j], b_off[j] + koff);
#pragma unroll
        for (int ni = 0; ni < 8; ni++) {
            const uint32_t b0 = Bf[ni >> 1][(ni & 1) * 2];
            const uint32_t b1 = Bf[ni >> 1][(ni & 1) * 2 + 1];
            mma_f16(acc[0][ni], A0, b0, b1);
            mma_f16(acc[1][ni], A1, b0, b1);
        }
    }

    // ---- single-pass staged epilogue (staging overlays tile smem) ----
    __syncthreads();   // all warps finished reading tiles
    float* wst = (float*)sm + wid * SWARP;    // [32 rows][SSTR floats]
    const float sc = 0.125f;

    // stage: lane l writes float2 at row r = mi*16 + h2*8 + (l>>2),
    //        col 8*ni + 2*(l&3)  (addr8B = 36r + 4ni + (l&3): conflict-free)
#pragma unroll
    for (int mi = 0; mi < 2; mi++)
#pragma unroll
        for (int h2 = 0; h2 < 2; h2++) {
            const int r = mi * 16 + h2 * 8 + (l >> 2);
#pragma unroll
            for (int ni = 0; ni < 8; ni++) {
                *(float2*)&wst[r * SSTR + ni * 8 + 2 * (l & 3)] =
                    make_float2(acc[mi][ni][h2 * 2 + 0] * sc,
                                acc[mi][ni][h2 * 2 + 1] * sc);
            }
        }
    __syncwarp();

    // store: lane l covers column pair n0w + {2l, 2l+1}, all 32 rows.
    const int q0w = qt * BM + wm * 32;
    const int n0w = kt * BN + wn * 64;
    const long long obase = dtab.out_base[b] + (long long)h * L * L;
    const int rmax = min(32, L - q0w);
    const int n = n0w + 2 * l;
    const float* src = wst + 2 * l;
    float* dst = out + obase + (long long)q0w * L + n;

    if (!(L & 1)) {
        // even L: obase, q*L, n all even -> 8B-aligned; n<L implies n+1<L
        if (n < L) {
#pragma unroll 8
            for (int r = 0; r < rmax; r++) {
                const float2 v = *(const float2*)(src + r * SSTR);
                __stcs((float2*)(dst + (long long)r * L), v);
            }
        }
    } else {
        const bool v0 = n < L, v1 = n + 1 < L;
#pragma unroll 8
        for (int r = 0; r < rmax; r++) {
            const float2 v = *(const float2*)(src + r * SSTR);
            float* p = dst + (long long)r * L;
            if (v0) __stcs(p, v.x);
            if (v1) __stcs(p + 1, v.y);
        }
    }
}

extern "C" void kernel_launch(void* const* d_in, const int* in_sizes, int n_in,
                              void* d_out, int out_size)
{
    const float* q = (const float*)d_in[0];
    const float* k = (const float*)d_in[1];
    float* o = (float*)d_out;

    constexpr Tables ht = make_tables();
    const int nblocks = ht.blk_base[NB];     // 5872

    // staging (8 * SWARP * 4 = 73728 B) overlays the 36864 B of tiles
    constexpr int smem = 8 * SWARP * (int)sizeof(float);   // 73728
    cudaFuncSetAttribute(bmm1_fp16,
                         cudaFuncAttributeMaxDynamicSharedMemorySize, smem);
    bmm1_fp16<<<nblocks, 256, smem>>>(q, k, o);
}